// round 10
// baseline (speedup 1.0000x reference)
#include <cuda_runtime.h>
#include <cuda_fp16.h>
#include <cstdint>

// ConvTranspose2D via 4 parity-class implicit GEMMs on mma.sync m16n8k16 fp16.
// out[co, 2i+ph, 2j+pw] = b[co] + sum_{ci,a,b} W[co,ci,2a+ph,2b+pw] * x[ci,i-1+a+ph,j-1+b+pw]
// Per class: M=128 (co), N=128 per i-row (j), K=1024 (ci*4 taps). Grid 128x4.
// 8 warps/CTA (256 thr), warp tile 64x32, fp32 accumulate, 2 CTAs/SM.

#define C_IN   256
#define C_OUT  128
#define H_IN   128
#define W_IN   128
#define H_OUT  256
#define K_TOT  1024
#define NCHUNK 32          // 32 k (8 ci) per chunk -> 2 k16-steps
#define XP_H   130
#define XP_W   132
#define XQ     33          // XP_W / 4 quads per row

#define NW_ELEM (4 * NCHUNK * 2048)
#define NW_BLK  (NW_ELEM / 256)                 // 1024
#define NX_QUAD (C_IN * XP_H * XQ)
#define NX_BLK  ((NX_QUAD + 255) / 256)

__device__ __forceinline__ uint32_t pack_half2(float a, float b) {
    uint32_t lo = (uint32_t)__half_as_ushort(__float2half_rn(a));
    uint32_t hi = (uint32_t)__half_as_ushort(__float2half_rn(b));
    return lo | (hi << 16);
}

// A images: per (cls, chunk): [8 mt8][2 ks][32 lane][4 reg] f16x2 words in exact
// m16n8k16 A-fragment order. 1 MB.
__device__ __align__(16) uint32_t g_Wimg[NW_ELEM];
// Overlapping-pair padded fp16 x image: word [ci][r][pc] = (xpad[r][pc-1], xpad[r][pc]).
__device__ __align__(16) uint32_t g_xph[C_IN * XP_H * XP_W];   // 17.6 MB

__global__ void prep_all(const float* __restrict__ Wg, const float* __restrict__ x) {
    if (blockIdx.x < NW_BLK) {
        int idx = blockIdx.x * 256 + threadIdx.x;
        int reg   = idx & 3;
        int lane  = (idx >> 2) & 31;
        int ks    = (idx >> 7) & 1;
        int mt8   = (idx >> 8) & 7;
        int chunk = (idx >> 11) & 31;
        int cls   = idx >> 16;
        int ph = cls >> 1, pw = cls & 1;

        int row   = (lane >> 2) + (reg & 1) * 8;       // 0..15
        int co    = mt8 * 16 + row;
        int kcol0 = (lane & 3) * 2 + (reg >> 1) * 8;   // 0..14 even
        int kl32  = ks * 16 + kcol0;
        int ci    = chunk * 8 + (kl32 >> 2);
        int a     = (kcol0 >> 1) & 1;

        const float* wbase = Wg + (co * C_IN + ci) * 16 + (2 * a + ph) * 4 + pw;
        g_Wimg[idx] = pack_half2(wbase[0], wbase[2]);   // (b=0, b=1)
    } else {
        int q = (blockIdx.x - NW_BLK) * 256 + threadIdx.x;
        if (q >= NX_QUAD) return;
        int ci  = q / (XP_H * XQ);
        int rem = q % (XP_H * XQ);
        int r   = rem / XQ;
        int pc0 = (rem % XQ) * 4;
        int ih  = r - 1;
        float xv[5];
        const bool rok = (unsigned)ih < (unsigned)H_IN;
        const float* xrow = x + (ci * H_IN + (rok ? ih : 0)) * W_IN;
        #pragma unroll
        for (int m = 0; m < 5; m++) {
            int iw = pc0 - 1 + m;
            xv[m] = (rok && (unsigned)iw < (unsigned)W_IN) ? xrow[iw] : 0.0f;
        }
        uint4 w;
        w.x = pack_half2(xv[0], xv[1]);
        w.y = pack_half2(xv[1], xv[2]);
        w.z = pack_half2(xv[2], xv[3]);
        w.w = pack_half2(xv[3], xv[4]);
        *reinterpret_cast<uint4*>(g_xph + ((size_t)ci * XP_H + r) * XP_W + pc0) = w;
    }
}

__device__ __forceinline__ uint32_t smem_u32(const void* p) {
    uint32_t a;
    asm("{ .reg .u64 t; cvta.to.shared.u64 t, %1; cvt.u32.u64 %0, t; }" : "=r"(a) : "l"(p));
    return a;
}

#define BPITCH 136   // u32 pitch for B rows (conflict-free: 136 % 32 == 8)

__global__ __launch_bounds__(256, 2)
void convT_mma(const float* __restrict__ bias, float* __restrict__ out) {
    __shared__ __align__(16) uint32_t Asm[2][2048];       // A frag images, 16 KB
    __shared__ __align__(16) uint32_t Bsm[2][16][BPITCH]; // [buf][h*8+p][j], ~17.4 KB

    const int cls = blockIdx.y;
    const int i   = blockIdx.x;
    const int ph  = cls >> 1, pw = cls & 1;
    const int tid = threadIdx.x;
    const int wid = tid >> 5, lid = tid & 31;
    const int wm  = wid >> 2;     // 0..1 -> co base wm*64
    const int wn  = wid & 3;      // 0..3 -> j  base wn*32

    float acc[4][4][4];
    #pragma unroll
    for (int mt = 0; mt < 4; mt++)
        #pragma unroll
        for (int nt = 0; nt < 4; nt++)
            #pragma unroll
            for (int q = 0; q < 4; q++) acc[mt][nt][q] = 0.0f;

    const uint32_t* Aimg = g_Wimg + (size_t)cls * NCHUNK * 2048;
    const uint32_t sA0 = smem_u32(&Asm[0][0]);
    const uint32_t sA1 = smem_u32(&Asm[1][0]);

    // B staging: thread = (h = tid>>7, j = tid&127); 8 words per thread.
    const int bj = tid & 127;
    const int bh = tid >> 7;
    uint32_t bv[8];

    #define CPA(c, sbuf)                                                       \
    {                                                                          \
        const uint32_t* src = Aimg + (c) * 2048 + tid * 4;                     \
        uint32_t dst = (sbuf) + tid * 16;                                      \
        _Pragma("unroll")                                                      \
        for (int u = 0; u < 2; u++)                                            \
            asm volatile("cp.async.ca.shared.global [%0], [%1], 16;"           \
                         :: "r"(dst + u * 4096), "l"(src + u * 1024));         \
        asm volatile("cp.async.commit_group;");                                \
    }

    // pair q: ci = c*8 + bh*4 + (q>>1), a = q&1.
    const uint32_t* xb = g_xph + (size_t)(i + ph) * XP_W + bj + pw;
    #define STAGEB(c)                                                          \
    {                                                                          \
        _Pragma("unroll")                                                      \
        for (int q = 0; q < 8; q++) {                                          \
            const int ci = (c) * 8 + bh * 4 + (q >> 1);                        \
            bv[q] = xb[((size_t)ci * XP_H + (q & 1)) * XP_W];                  \
        }                                                                      \
    }

    // NOTE: inner loop var must NOT shadow the pipeline var `p` (macro capture!)
    #define STOREB(buf)                                                        \
    {                                                                          \
        _Pragma("unroll")                                                      \
        for (int q = 0; q < 8; q++) Bsm[buf][bh * 8 + q][bj] = bv[q];          \
    }

    // ---- prologue ----
    CPA(0, sA0);
    STAGEB(0);
    asm volatile("cp.async.wait_group 0;" ::: "memory");
    STOREB(0);
    __syncthreads();

    int p = 0;
    for (int c = 0; c < NCHUNK; c++) {
        if (c + 1 < NCHUNK) {
            CPA(c + 1, p ? sA0 : sA1);
            STAGEB(c + 1);
        }

        const uint32_t* Ab = Asm[p];
        #pragma unroll
        for (int ks = 0; ks < 2; ks++) {
            uint4 af[4];
            #pragma unroll
            for (int mt = 0; mt < 4; mt++)
                af[mt] = reinterpret_cast<const uint4*>(Ab)
                             [((wm * 4 + mt) * 2 + ks) * 32 + lid];
            uint32_t b0[4], b1[4];
            #pragma unroll
            for (int nt = 0; nt < 4; nt++) {
                const int jc = wn * 32 + nt * 8 + (lid >> 2);
                b0[nt] = Bsm[p][ks * 8 + (lid & 3)][jc];
                b1[nt] = Bsm[p][ks * 8 + (lid & 3) + 4][jc];
            }
            #pragma unroll
            for (int mt = 0; mt < 4; mt++)
                #pragma unroll
                for (int nt = 0; nt < 4; nt++)
                    asm volatile(
                        "mma.sync.aligned.m16n8k16.row.col.f32.f16.f16.f32 "
                        "{%0,%1,%2,%3}, {%4,%5,%6,%7}, {%8,%9}, {%0,%1,%2,%3};"
                        : "+f"(acc[mt][nt][0]), "+f"(acc[mt][nt][1]),
                          "+f"(acc[mt][nt][2]), "+f"(acc[mt][nt][3])
                        : "r"(af[mt].x), "r"(af[mt].y), "r"(af[mt].z), "r"(af[mt].w),
                          "r"(b0[nt]), "r"(b1[nt]));
        }

        if (c + 1 < NCHUNK) {
            STOREB(p ^ 1);               // safe: compute(c) only read buf p
            asm volatile("cp.async.wait_group 0;" ::: "memory");
            __syncthreads();             // single barrier per chunk
        }
        p ^= 1;
    }

    // ---- epilogue: bias + stride-2 scatter ----
    const int oh = 2 * i + ph;
    #pragma unroll
    for (int mt = 0; mt < 4; mt++) {
        const int co0 = wm * 64 + mt * 16 + (lid >> 2);
        const int co1 = co0 + 8;
        const float bv0 = bias[co0];
        const float bv1 = bias[co1];
        float* r0 = out + ((size_t)co0 * H_OUT + oh) * H_OUT + pw;
        float* r1 = out + ((size_t)co1 * H_OUT + oh) * H_OUT + pw;
        #pragma unroll
        for (int nt = 0; nt < 4; nt++) {
            const int j0 = wn * 32 + nt * 8 + 2 * (lid & 3);
            r0[2 * j0]       = acc[mt][nt][0] + bv0;
            r0[2 * (j0 + 1)] = acc[mt][nt][1] + bv0;
            r1[2 * j0]       = acc[mt][nt][2] + bv1;
            r1[2 * (j0 + 1)] = acc[mt][nt][3] + bv1;
        }
    }
}

extern "C" void kernel_launch(void* const* d_in, const int* in_sizes, int n_in,
                              void* d_out, int out_size) {
    const float* x  = (const float*)d_in[0];   // 256*128*128
    const float* Wg = (const float*)d_in[1];   // 128*256*4*4
    const float* b  = (const float*)d_in[2];   // 128
    float* out = (float*)d_out;                // 128*256*256

    prep_all<<<NW_BLK + NX_BLK, 256>>>(Wg, x);

    dim3 grid(H_IN, 4);
    convT_mma<<<grid, 256>>>(b, out);
}

// round 11
// speedup vs baseline: 1.0432x; 1.0432x over previous
#include <cuda_runtime.h>
#include <cuda_fp16.h>
#include <cstdint>

// ConvTranspose2D via 4 parity-class implicit GEMMs on mma.sync m16n8k16 fp16.
// out[co, 2i+ph, 2j+pw] = b[co] + sum_{ci,a,b} W[co,ci,2a+ph,2b+pw] * x[ci,i-1+a+ph,j-1+b+pw]
// Per class: M=128 (co), N=128 per i-row (j), K=1024 (ci*4 taps). Grid 128x4.
// 4 warps/CTA (128 thr), warp tile 64x64, 3-stage full-cp.async pipeline.

#define C_IN   256
#define C_OUT  128
#define H_IN   128
#define W_IN   128
#define H_OUT  256
#define K_TOT  1024
#define NCHUNK 32          // 32 k (8 ci) per chunk -> 2 k16-steps
#define XP_H   130
#define XP_W   132
#define XQ     33

#define NW_ELEM (4 * NCHUNK * 2048)
#define NW_BLK  (NW_ELEM / 256)
#define NX_QUAD (C_IN * XP_H * XQ)
#define NX_BLK  ((NX_QUAD + 255) / 256)

#define BPITCH 136                         // u32 pitch, conflict-free rows
#define SSTAGE (2048 + 16 * BPITCH)        // u32 per stage: A 8KB + B 8.5KB
#define NSTAGE 3
#define SMEM_BYTES (NSTAGE * SSTAGE * 4)   // 50688

__device__ __forceinline__ uint32_t pack_half2(float a, float b) {
    uint32_t lo = (uint32_t)__half_as_ushort(__float2half_rn(a));
    uint32_t hi = (uint32_t)__half_as_ushort(__float2half_rn(b));
    return lo | (hi << 16);
}

// A images: per (cls, chunk): [8 mt8][2 ks][32 lane][4 reg] f16x2 words in exact
// m16n8k16 A-fragment order. 1 MB.
__device__ __align__(16) uint32_t g_Wimg[NW_ELEM];
// Overlapping-pair padded fp16 x image: word [ci][r][pc] = (xpad[r][pc-1], xpad[r][pc]).
__device__ __align__(16) uint32_t g_xph[C_IN * XP_H * XP_W];   // 17.6 MB

__global__ void prep_all(const float* __restrict__ Wg, const float* __restrict__ x) {
    if (blockIdx.x < NW_BLK) {
        int idx = blockIdx.x * 256 + threadIdx.x;
        int reg   = idx & 3;
        int lane  = (idx >> 2) & 31;
        int ks    = (idx >> 7) & 1;
        int mt8   = (idx >> 8) & 7;
        int chunk = (idx >> 11) & 31;
        int cls   = idx >> 16;
        int ph = cls >> 1, pw = cls & 1;

        int row   = (lane >> 2) + (reg & 1) * 8;       // 0..15
        int co    = mt8 * 16 + row;
        int kcol0 = (lane & 3) * 2 + (reg >> 1) * 8;   // 0..14 even
        int kl32  = ks * 16 + kcol0;
        int ci    = chunk * 8 + (kl32 >> 2);
        int a     = (kcol0 >> 1) & 1;

        const float* wbase = Wg + (co * C_IN + ci) * 16 + (2 * a + ph) * 4 + pw;
        g_Wimg[idx] = pack_half2(wbase[0], wbase[2]);   // (b=0, b=1)
    } else {
        int q = (blockIdx.x - NW_BLK) * 256 + threadIdx.x;
        if (q >= NX_QUAD) return;
        int ci  = q / (XP_H * XQ);
        int rem = q % (XP_H * XQ);
        int r   = rem / XQ;
        int pc0 = (rem % XQ) * 4;
        int ih  = r - 1;
        float xv[5];
        const bool rok = (unsigned)ih < (unsigned)H_IN;
        const float* xrow = x + (ci * H_IN + (rok ? ih : 0)) * W_IN;
        #pragma unroll
        for (int m = 0; m < 5; m++) {
            int iw = pc0 - 1 + m;
            xv[m] = (rok && (unsigned)iw < (unsigned)W_IN) ? xrow[iw] : 0.0f;
        }
        uint4 w;
        w.x = pack_half2(xv[0], xv[1]);
        w.y = pack_half2(xv[1], xv[2]);
        w.z = pack_half2(xv[2], xv[3]);
        w.w = pack_half2(xv[3], xv[4]);
        *reinterpret_cast<uint4*>(g_xph + ((size_t)ci * XP_H + r) * XP_W + pc0) = w;
    }
}

__device__ __forceinline__ uint32_t smem_u32(const void* p) {
    uint32_t a;
    asm("{ .reg .u64 t; cvta.to.shared.u64 t, %1; cvt.u32.u64 %0, t; }" : "=r"(a) : "l"(p));
    return a;
}

__global__ __launch_bounds__(128, 2)
void convT_mma(const float* __restrict__ bias, float* __restrict__ out) {
    extern __shared__ __align__(16) uint32_t smem[];   // NSTAGE * SSTAGE u32

    const int cls = blockIdx.y;
    const int i   = blockIdx.x;
    const int ph  = cls >> 1, pw = cls & 1;
    const int tid = threadIdx.x;
    const int wid = tid >> 5, lid = tid & 31;
    const int wm  = wid >> 1;     // 0..1 -> co base wm*64
    const int wn  = wid & 1;      // 0..1 -> j  base wn*64

    float acc[4][8][4];
    #pragma unroll
    for (int mt = 0; mt < 4; mt++)
        #pragma unroll
        for (int nt = 0; nt < 8; nt++)
            #pragma unroll
            for (int q = 0; q < 4; q++) acc[mt][nt][q] = 0.0f;

    const uint32_t* Aimg = g_Wimg + (size_t)cls * NCHUNK * 2048;
    const uint32_t sbase = smem_u32(smem);

    // Prefetch chunk c into stage c % NSTAGE: A (4 x 16B) + B (16 x 4B) per thread.
    const uint32_t* xb = g_xph + (size_t)(i + ph) * XP_W + tid + pw;
    #define PREFETCH(c)                                                        \
    {                                                                          \
        const uint32_t st = sbase + ((c) % NSTAGE) * (SSTAGE * 4);             \
        const uint32_t* asrc = Aimg + (c) * 2048 + tid * 4;                    \
        const uint32_t adst = st + tid * 16;                                   \
        _Pragma("unroll")                                                      \
        for (int u = 0; u < 4; u++)                                            \
            asm volatile("cp.async.ca.shared.global [%0], [%1], 16;"           \
                         :: "r"(adst + u * 2048), "l"(asrc + u * 512));        \
        const uint32_t bdst = st + 2048 * 4 + tid * 4;                         \
        _Pragma("unroll")                                                      \
        for (int q = 0; q < 16; q++) {                                         \
            const int ci = (c) * 8 + ((q >> 3) * 4) + ((q & 7) >> 1);          \
            const uint32_t* bsrc = xb + ((size_t)ci * XP_H + (q & 1)) * XP_W;  \
            asm volatile("cp.async.ca.shared.global [%0], [%1], 4;"            \
                         :: "r"(bdst + q * (BPITCH * 4)), "l"(bsrc));          \
        }                                                                      \
        asm volatile("cp.async.commit_group;");                                \
    }

    // ---- prologue: stages 0..NSTAGE-2 ----
    PREFETCH(0);
    PREFETCH(1);

    for (int c = 0; c < NCHUNK; c++) {
        // group c was issued 2 chunks ago; allow 1 newer pending (none at tail).
        if (c < NCHUNK - 1)
            asm volatile("cp.async.wait_group 1;" ::: "memory");
        else
            asm volatile("cp.async.wait_group 0;" ::: "memory");
        __syncthreads();   // data visible to all; all warps done reading stage (c-1)%3

        if (c + NSTAGE - 1 < NCHUNK) PREFETCH(c + NSTAGE - 1);

        const uint32_t* Ab  = smem + (c % NSTAGE) * SSTAGE;
        const uint32_t* Bst = Ab + 2048;
        #pragma unroll
        for (int ks = 0; ks < 2; ks++) {
            uint4 af[4];
            #pragma unroll
            for (int mt = 0; mt < 4; mt++)
                af[mt] = reinterpret_cast<const uint4*>(Ab)
                             [((wm * 4 + mt) * 2 + ks) * 32 + lid];
            uint32_t b0[8], b1[8];
            #pragma unroll
            for (int nt = 0; nt < 8; nt++) {
                const int jc = wn * 64 + nt * 8 + (lid >> 2);
                b0[nt] = Bst[(ks * 8 + (lid & 3)) * BPITCH + jc];
                b1[nt] = Bst[(ks * 8 + (lid & 3) + 4) * BPITCH + jc];
            }
            #pragma unroll
            for (int mt = 0; mt < 4; mt++)
                #pragma unroll
                for (int nt = 0; nt < 8; nt++)
                    asm volatile(
                        "mma.sync.aligned.m16n8k16.row.col.f32.f16.f16.f32 "
                        "{%0,%1,%2,%3}, {%4,%5,%6,%7}, {%8,%9}, {%0,%1,%2,%3};"
                        : "+f"(acc[mt][nt][0]), "+f"(acc[mt][nt][1]),
                          "+f"(acc[mt][nt][2]), "+f"(acc[mt][nt][3])
                        : "r"(af[mt].x), "r"(af[mt].y), "r"(af[mt].z), "r"(af[mt].w),
                          "r"(b0[nt]), "r"(b1[nt]));
        }
    }

    // ---- epilogue: bias + stride-2 scatter ----
    const int oh = 2 * i + ph;
    #pragma unroll
    for (int mt = 0; mt < 4; mt++) {
        const int co0 = wm * 64 + mt * 16 + (lid >> 2);
        const int co1 = co0 + 8;
        const float bv0 = bias[co0];
        const float bv1 = bias[co1];
        float* r0 = out + ((size_t)co0 * H_OUT + oh) * H_OUT + pw;
        float* r1 = out + ((size_t)co1 * H_OUT + oh) * H_OUT + pw;
        #pragma unroll
        for (int nt = 0; nt < 8; nt++) {
            const int j0 = wn * 64 + nt * 8 + 2 * (lid & 3);
            r0[2 * j0]       = acc[mt][nt][0] + bv0;
            r0[2 * (j0 + 1)] = acc[mt][nt][1] + bv0;
            r1[2 * j0]       = acc[mt][nt][2] + bv1;
            r1[2 * (j0 + 1)] = acc[mt][nt][3] + bv1;
        }
    }
}

extern "C" void kernel_launch(void* const* d_in, const int* in_sizes, int n_in,
                              void* d_out, int out_size) {
    const float* x  = (const float*)d_in[0];   // 256*128*128
    const float* Wg = (const float*)d_in[1];   // 128*256*4*4
    const float* b  = (const float*)d_in[2];   // 128
    float* out = (float*)d_out;                // 128*256*256

    cudaFuncSetAttribute(convT_mma, cudaFuncAttributeMaxDynamicSharedMemorySize,
                         SMEM_BYTES);

    prep_all<<<NW_BLK + NX_BLK, 256>>>(Wg, x);

    dim3 grid(H_IN, 4);
    convT_mma<<<grid, 128, SMEM_BYTES>>>(b, out);
}